// round 15
// baseline (speedup 1.0000x reference)
#include <cuda_runtime.h>
#include <cuda_fp16.h>
#include <math.h>
#include <stdint.h>

#define B_ 2
#define T_ 2048
#define C_ 2048
#define H_ 16
#define D_ 128
#define M_ (B_*T_)            /* 4096 */
#define N1_ (3*C_)            /* 6144 */
#define NKV (B_*H_*T_*D_)     /* 8388608 */

// Scratch (allocation-free)
__device__ __half g_xh[M_*C_];       // x  fp16
__device__ __half g_wqkvt[N1_*C_];   // W_qkv^T [n][k] fp16
__device__ __half g_woutt[C_*C_];    // W_out^T [n][k] fp16
__device__ __half g_qh[NKV];
__device__ __half g_kh[NKV];
__device__ __half g_vh[NKV];
__device__ float  g_k[NKV];          // fp32 k fallback
__device__ float  g_v[NKV];          // fp32 v fallback
__device__ __half g_attnh[M_*C_];    // attention out fp16

// ---------------------------------------------------------------------------
// Helpers
// ---------------------------------------------------------------------------
__device__ __forceinline__ uint32_t smem_u32(const void* p) {
    uint32_t a;
    asm("{ .reg .u64 t; cvta.to.shared.u64 t, %1; cvt.u32.u64 %0, t; }"
        : "=r"(a) : "l"(p));
    return a;
}
__device__ __forceinline__ void cpasync16(uint32_t dst, const void* src) {
    asm volatile("cp.async.cg.shared.global [%0], [%1], 16;"
                 :: "r"(dst), "l"(src) : "memory");
}
#define CP_COMMIT() asm volatile("cp.async.commit_group;" ::: "memory")
__device__ __forceinline__ void ldsm4(uint32_t* r, uint32_t a) {
    asm volatile("ldmatrix.sync.aligned.m8n8.x4.shared.b16 {%0,%1,%2,%3}, [%4];"
                 : "=r"(r[0]), "=r"(r[1]), "=r"(r[2]), "=r"(r[3]) : "r"(a));
}
__device__ __forceinline__ void ldsm4t(uint32_t* r, uint32_t a) {
    asm volatile("ldmatrix.sync.aligned.m8n8.x4.trans.shared.b16 {%0,%1,%2,%3}, [%4];"
                 : "=r"(r[0]), "=r"(r[1]), "=r"(r[2]), "=r"(r[3]) : "r"(a));
}
__device__ __forceinline__ void mma16(float* d, const uint32_t* a,
                                      const uint32_t* b) {
    asm volatile(
        "mma.sync.aligned.m16n8k16.row.col.f32.f16.f16.f32 "
        "{%0,%1,%2,%3}, {%4,%5,%6,%7}, {%8,%9}, {%0,%1,%2,%3};"
        : "+f"(d[0]), "+f"(d[1]), "+f"(d[2]), "+f"(d[3])
        : "r"(a[0]), "r"(a[1]), "r"(a[2]), "r"(a[3]), "r"(b[0]), "r"(b[1]));
}
__device__ __forceinline__ uint32_t packh2(float lo, float hi) {
    __half2 h = __floats2half2_rn(lo, hi);
    return *(uint32_t*)&h;
}
// pack (lo,hi) fp32 -> f16x2 then 2^x on both halves (single MUFU op)
__device__ __forceinline__ uint32_t exp2_f16x2(float lo, float hi) {
    uint32_t h, r;
    asm("cvt.rn.f16x2.f32 %0, %1, %2;" : "=r"(h) : "f"(hi), "f"(lo));
    asm("ex2.approx.f16x2 %0, %1;" : "=r"(r) : "r"(h));
    return r;
}
// packed f32x2 (sm_100+ family-common)
__device__ __forceinline__ uint64_t pk2(float lo, float hi) {
    uint64_t v;
    asm("mov.b64 %0, {%1, %2};" : "=l"(v) : "f"(lo), "f"(hi));
    return v;
}
__device__ __forceinline__ void upk2(uint64_t v, float& lo, float& hi) {
    asm("mov.b64 {%0, %1}, %2;" : "=f"(lo), "=f"(hi) : "l"(v));
}
__device__ __forceinline__ uint64_t mul2(uint64_t a, uint64_t b) {
    uint64_t d;
    asm("mul.rn.f32x2 %0, %1, %2;" : "=l"(d) : "l"(a), "l"(b));
    return d;
}
__device__ __forceinline__ void redadd(float* p, float v) {
    asm volatile("red.global.add.f32 [%0], %1;" :: "l"(p), "f"(v) : "memory");
}

// ---------------------------------------------------------------------------
// Fused prep: cvt x->f16, transpose+cvt weights, bias-init of out (for the
// split-K atomic out-proj). Block ranges:
//   [0, 6144)      wqkv transpose | [6144, 8192) wout transpose
//   [8192, 9216)   x conversion   | [9216, 10240) out[m][n] = bias[n]
// ---------------------------------------------------------------------------
__device__ __forceinline__ void transpose_body(
    const float* __restrict__ W, __half* __restrict__ Wt, int K, int N,
    int nb, int kb, float (*tile)[33])
{
    const int k0 = kb << 6, n0 = nb << 5;
    const int tx = threadIdx.x & 31, ty = threadIdx.x >> 5;
    #pragma unroll
    for (int j = 0; j < 8; j++) {
        const int kr = j * 8 + ty;
        tile[kr][tx] = __ldg(W + (size_t)(k0 + kr) * N + n0 + tx);
    }
    __syncthreads();
    #pragma unroll
    for (int j = 0; j < 4; j++) {
        const int nr = j * 8 + ty;
        const int k2 = tx * 2;
        const uint32_t p = packh2(tile[k2][nr], tile[k2 + 1][nr]);
        *(uint32_t*)&Wt[(size_t)(n0 + nr) * K + k0 + k2] = p;
    }
}

__global__ void __launch_bounds__(256) prep_kernel(
    const float* __restrict__ x,
    const float* __restrict__ Wqkv,
    const float* __restrict__ Wout,
    const float* __restrict__ b_out,
    float* __restrict__ out)
{
    __shared__ float tile[64][33];
    const int bid = blockIdx.x;
    if (bid < 6144) {
        transpose_body(Wqkv, g_wqkvt, C_, N1_, bid % 192, bid / 192, tile);
    } else if (bid < 8192) {
        const int r = bid - 6144;
        transpose_body(Wout, g_woutt, C_, C_, r & 63, r >> 6, tile);
    } else if (bid < 9216) {
        const int n4 = (M_ * C_) / 4;
        for (int i = (bid - 8192) * 256 + threadIdx.x; i < n4; i += 1024 * 256) {
            float4 v = __ldg((const float4*)x + i);
            uint2 o;
            o.x = packh2(v.x, v.y);
            o.y = packh2(v.z, v.w);
            ((uint2*)g_xh)[i] = o;
        }
    } else {
        // out[m][n] = bias[n]; 8.4M floats as float4
        const int n4 = (M_ * C_) / 4;
        for (int i = (bid - 9216) * 256 + threadIdx.x; i < n4; i += 1024 * 256) {
            const int nc = (i * 4) & 2047;
            ((float4*)out)[i] = *(const float4*)(b_out + nc);
        }
    }
}

// ---------------------------------------------------------------------------
// fp16 mma.sync GEMM. CTA 128x128, BK=32, 4 warps (64x64 warp tile),
// 3-stage cp.async, 3 CTAs/SM. MODE 0: scatter qkv (gridDim.z==1).
// MODE 1: split-K over gridDim.z; partials combined with red.global.add
// into a bias-preinitialized output.
// ---------------------------------------------------------------------------
#define GSTG 20480
#define GEMM_SMEM (3 * GSTG)

template <int MODE>
__global__ void __launch_bounds__(128, 3) hgemm_kernel(
    const __half* __restrict__ Ag, const __half* __restrict__ Bt,
    const float* __restrict__ bias, float* __restrict__ Cout,
    float* __restrict__ Kout, float* __restrict__ Vout)
{
    extern __shared__ char dynsm[];
    const uint32_t smb = smem_u32(dynsm);
    const int tid  = threadIdx.x;
    const int lane = tid & 31;
    const int warp = tid >> 5;
    const int wm = warp & 1, wn = warp >> 1;
    const int bm = blockIdx.y << 7, bn = blockIdx.x << 7;
    const int lg = lane >> 2, lp = lane & 3;
    const int NIT = (2048 / 32) / gridDim.z;
    const int kb0 = blockIdx.z * NIT;

    float acc[4][8][4];
    #pragma unroll
    for (int mt = 0; mt < 4; mt++)
        #pragma unroll
        for (int nt = 0; nt < 8; nt++)
            #pragma unroll
            for (int i = 0; i < 4; i++) acc[mt][nt][i] = 0.f;

    const int l_row = tid >> 2;
    const int l_seg = tid & 3;
    auto load_tiles = [&](int it, int s) {
        const uint32_t base = smb + s * GSTG;
        #pragma unroll
        for (int j = 0; j < 4; j++) {
            const int row = l_row + 32 * j;
            cpasync16(base + row * 80 + l_seg * 16,
                      Ag + (size_t)(bm + row) * 2048 + (kb0 + it) * 32 + l_seg * 8);
            cpasync16(base + 10240 + row * 80 + l_seg * 16,
                      Bt + (size_t)(bn + row) * 2048 + (kb0 + it) * 32 + l_seg * 8);
        }
        CP_COMMIT();
    };

    const uint32_t a_off = (lane & 15) * 80 + (lane >> 4) * 16;
    const uint32_t b_off = ((lane & 7) + ((lane >> 4) & 1) * 8) * 80
                           + ((lane >> 3) & 1) * 16;

    load_tiles(0, 0);
    load_tiles(1, 1);

    #pragma unroll 1
    for (int it = 0; it < NIT; it++) {
        if (it + 2 < NIT)
            asm volatile("cp.async.wait_group 1;" ::: "memory");
        else
            asm volatile("cp.async.wait_group 0;" ::: "memory");
        __syncthreads();

        const int s = it % 3;
        const uint32_t smA = smb + s * GSTG + wm * 64 * 80 + a_off;
        const uint32_t smB = smb + s * GSTG + 10240 + wn * 64 * 80 + b_off;

        uint32_t a0[4][4], b0[4][4];
        #pragma unroll
        for (int mt = 0; mt < 4; mt++)
            ldsm4(a0[mt], smA + mt * 16 * 80);
        #pragma unroll
        for (int np = 0; np < 4; np++)
            ldsm4(b0[np], smB + np * 16 * 80);

        if (it + 2 < NIT) load_tiles(it + 2, (it + 2) % 3);

        #pragma unroll
        for (int mt = 0; mt < 4; mt++)
            #pragma unroll
            for (int np = 0; np < 4; np++) {
                mma16(acc[mt][2 * np],     a0[mt], b0[np]);
                mma16(acc[mt][2 * np + 1], a0[mt], b0[np] + 2);
            }

        uint32_t a1[4][4], b1[4][4];
        #pragma unroll
        for (int mt = 0; mt < 4; mt++)
            ldsm4(a1[mt], smA + mt * 16 * 80 + 32);
        #pragma unroll
        for (int np = 0; np < 4; np++)
            ldsm4(b1[np], smB + np * 16 * 80 + 32);
        #pragma unroll
        for (int mt = 0; mt < 4; mt++)
            #pragma unroll
            for (int np = 0; np < 4; np++) {
                mma16(acc[mt][2 * np],     a1[mt], b1[np]);
                mma16(acc[mt][2 * np + 1], a1[mt], b1[np] + 2);
            }
    }

    // Epilogue
    #pragma unroll
    for (int mt = 0; mt < 4; mt++) {
        #pragma unroll
        for (int half = 0; half < 2; half++) {
            const int m = bm + wm * 64 + mt * 16 + lg + half * 8;
            #pragma unroll
            for (int nt = 0; nt < 8; nt++) {
                const int n = bn + wn * 64 + nt * 8 + 2 * lp;
                if (MODE == 0) {
                    float2 bv = *(const float2*)(bias + n);
                    const float o0 = acc[mt][nt][half * 2 + 0] + bv.x;
                    const float o1 = acc[mt][nt][half * 2 + 1] + bv.y;
                    const int which = n >> 11;
                    const int h = (n & 2047) >> 7;
                    const int d = n & 127;
                    const int bi = m >> 11, t2 = m & 2047;
                    const size_t idx = (((size_t)bi * H_ + h) * T_ + t2) * D_ + d;
                    const uint32_t p = packh2(o0, o1);
                    if (which == 0) {
                        *(uint32_t*)&g_qh[idx] = p;
                    } else if (which == 1) {
                        *(uint32_t*)&g_kh[idx] = p;
                        *(float2*)&Kout[idx] = make_float2(o0, o1);
                    } else {
                        *(uint32_t*)&g_vh[idx] = p;
                        *(float2*)&Vout[idx] = make_float2(o0, o1);
                    }
                } else {
                    // split-K partial: bias already pre-initialized in out
                    float* dst = Cout + (size_t)m * 2048 + n;
                    redadd(dst,     acc[mt][nt][half * 2 + 0]);
                    redadd(dst + 1, acc[mt][nt][half * 2 + 1]);
                }
            }
        }
    }
}

// ---------------------------------------------------------------------------
// fp16 flash attention, causal. Br=128 (8 warps x 16 rows), Bc=32, D=128.
// Q frags ks=0..3 register-cached; exp via ex2.approx.f16x2; accO rescale
// via packed mul.rn.f32x2.
// ---------------------------------------------------------------------------
#define AQ_BYTES (128 * 272)
#define AKV_BYTES (32 * 272)
#define ATTN_SMEM (AQ_BYTES + 4 * AKV_BYTES)

__global__ void __launch_bounds__(256, 2) attn_tc_kernel()
{
    extern __shared__ char dynsm[];
    const uint32_t smb = smem_u32(dynsm);
    const uint32_t smQ = smb;

    const int it  = (gridDim.x - 1) - blockIdx.x;
    const int bh  = blockIdx.y;
    const int tid = threadIdx.x;
    const int lane = tid & 31;
    const int w   = tid >> 5;
    const int lg = lane >> 2, lp = lane & 3;
    const int r0 = w * 16;

    const __half* Qg = g_qh + (size_t)bh * (T_ * D_);
    const __half* Kg = g_kh + (size_t)bh * (T_ * D_);
    const __half* Vg = g_vh + (size_t)bh * (T_ * D_);

    {
        const int row = tid >> 1;
        const int s0 = (tid & 1) * 8;
        #pragma unroll
        for (int j = 0; j < 8; j++)
            cpasync16(smQ + row * 272 + (s0 + j) * 16,
                      Qg + (size_t)(it * 128 + row) * 128 + (s0 + j) * 8);
    }
    const int kv_row = tid >> 3;
    const int kv_s0 = (tid & 7) * 2;
    auto load_kv = [&](int jt, int st) {
        const uint32_t smK = smb + AQ_BYTES + st * AKV_BYTES;
        const uint32_t smV = smb + AQ_BYTES + 2 * AKV_BYTES + st * AKV_BYTES;
        #pragma unroll
        for (int j = 0; j < 2; j++) {
            const int seg = kv_s0 + j;
            cpasync16(smK + kv_row * 272 + seg * 16,
                      Kg + (size_t)(jt * 32 + kv_row) * 128 + seg * 8);
            cpasync16(smV + kv_row * 272 + seg * 16,
                      Vg + (size_t)(jt * 32 + kv_row) * 128 + seg * 8);
        }
        CP_COMMIT();
    };
    load_kv(0, 0);   // group 0 = Q + KV0

    const uint32_t q_off = (r0 + (lane & 15)) * 272 + (lane >> 4) * 16;
    const uint32_t k_off = ((lane & 7) + ((lane >> 4) & 1) * 8) * 272
                           + ((lane >> 3) & 1) * 16;
    const uint32_t v_off = ((lane & 7) + ((lane >> 3) & 1) * 8) * 272
                           + (lane >> 4) * 16;

    asm volatile("cp.async.wait_group 0;" ::: "memory");
    __syncthreads();
    load_kv(1, 1);   // jmax >= 3 always

    uint32_t qc[4][4];
    #pragma unroll
    for (int ks = 0; ks < 4; ks++)
        ldsm4(qc[ks], smQ + q_off + ks * 32);

    float accO[16][4];
    #pragma unroll
    for (int nt = 0; nt < 16; nt++)
        #pragma unroll
        for (int i = 0; i < 4; i++) accO[nt][i] = 0.f;
    float m0 = -INFINITY, m1 = -INFINITY, l0 = 0.f, l1 = 0.f;
    const float scale = 0.08838834764831845f;
    const float L2E = 1.4426950408889634f;
    const int jmax = 4 * it + 3;
    const int rq0 = it * 128 + r0 + lg;
    const int rq1 = rq0 + 8;

    for (int jt = 0; jt <= jmax; jt++) {
        const int cur = jt & 1;
        if (jt > 0) {
            asm volatile("cp.async.wait_group 0;" ::: "memory");
            __syncthreads();
            if (jt < jmax) load_kv(jt + 1, cur ^ 1);
        }

        if (jt * 32 > it * 128 + r0 + 15) continue;

        const uint32_t smK = smb + AQ_BYTES + cur * AKV_BYTES;
        const uint32_t smV = smb + AQ_BYTES + 2 * AKV_BYTES + cur * AKV_BYTES;

        float accS[4][4];
        #pragma unroll
        for (int nt = 0; nt < 4; nt++)
            #pragma unroll
            for (int i = 0; i < 4; i++) accS[nt][i] = 0.f;
        #pragma unroll
        for (int ks = 0; ks < 8; ks++) {
            uint32_t qa[4];
            if (ks < 4) {
                qa[0] = qc[ks][0]; qa[1] = qc[ks][1];
                qa[2] = qc[ks][2]; qa[3] = qc[ks][3];
            } else {
                ldsm4(qa, smQ + q_off + ks * 32);
            }
            #pragma unroll
            for (int np = 0; np < 2; np++) {
                uint32_t kb[4];
                ldsm4(kb, smK + np * 16 * 272 + k_off + ks * 32);
                mma16(accS[2 * np],     qa, kb);
                mma16(accS[2 * np + 1], qa, kb + 2);
            }
        }

        if (jt * 32 + 31 > it * 128 + r0) {
            #pragma unroll
            for (int nt = 0; nt < 4; nt++) {
                #pragma unroll
                for (int jj = 0; jj < 2; jj++) {
                    const int ck = jt * 32 + 8 * nt + 2 * lp + jj;
                    accS[nt][jj]     = (ck > rq0) ? -INFINITY
                                                  : accS[nt][jj] * scale;
                    accS[nt][jj + 2] = (ck > rq1) ? -INFINITY
                                                  : accS[nt][jj + 2] * scale;
                }
            }
        } else {
            #pragma unroll
            for (int nt = 0; nt < 4; nt++)
                #pragma unroll
                for (int i = 0; i < 4; i++) accS[nt][i] *= scale;
        }

        float mx0 = -INFINITY, mx1 = -INFINITY;
        #pragma unroll
        for (int nt = 0; nt < 4; nt++) {
            mx0 = fmaxf(mx0, fmaxf(accS[nt][0], accS[nt][1]));
            mx1 = fmaxf(mx1, fmaxf(accS[nt][2], accS[nt][3]));
        }
        mx0 = fmaxf(mx0, __shfl_xor_sync(0xffffffffu, mx0, 1));
        mx0 = fmaxf(mx0, __shfl_xor_sync(0xffffffffu, mx0, 2));
        mx1 = fmaxf(mx1, __shfl_xor_sync(0xffffffffu, mx1, 1));
        mx1 = fmaxf(mx1, __shfl_xor_sync(0xffffffffu, mx1, 2));
        const float mn0 = fmaxf(m0, mx0), mn1 = fmaxf(m1, mx1);
        const float al0 = __expf(m0 - mn0), al1 = __expf(m1 - mn1);
        const float nb0 = -mn0 * L2E, nb1 = -mn1 * L2E;

        uint32_t pah[8];
        float s0 = 0.f, s1 = 0.f;
        #pragma unroll
        for (int nt = 0; nt < 4; nt++) {
            const float t0 = fmaf(accS[nt][0], L2E, nb0);
            const float t1 = fmaf(accS[nt][1], L2E, nb0);
            const float t2 = fmaf(accS[nt][2], L2E, nb1);
            const float t3 = fmaf(accS[nt][3], L2E, nb1);
            pah[2 * nt]     = exp2_f16x2(t0, t1);
            pah[2 * nt + 1] = exp2_f16x2(t2, t3);
            float2 f01 = __half22float2(*(__half2*)&pah[2 * nt]);
            float2 f23 = __half22float2(*(__half2*)&pah[2 * nt + 1]);
            s0 += f01.x + f01.y;
            s1 += f23.x + f23.y;
        }
        s0 += __shfl_xor_sync(0xffffffffu, s0, 1);
        s0 += __shfl_xor_sync(0xffffffffu, s0, 2);
        s1 += __shfl_xor_sync(0xffffffffu, s1, 1);
        s1 += __shfl_xor_sync(0xffffffffu, s1, 2);
        l0 = l0 * al0 + s0; m0 = mn0;
        l1 = l1 * al1 + s1; m1 = mn1;

        // accO rescale via packed f32x2 (halves FFMA count)
        const uint64_t A0 = pk2(al0, al0), A1 = pk2(al1, al1);
        #pragma unroll
        for (int nt = 0; nt < 16; nt++) {
            uint64_t v0 = pk2(accO[nt][0], accO[nt][1]);
            uint64_t v1 = pk2(accO[nt][2], accO[nt][3]);
            v0 = mul2(v0, A0);
            v1 = mul2(v1, A1);
            upk2(v0, accO[nt][0], accO[nt][1]);
            upk2(v1, accO[nt][2], accO[nt][3]);
        }

        #pragma unroll
        for (int s = 0; s < 2; s++) {
            #pragma unroll
            for (int np = 0; np < 8; np++) {
                uint32_t vb[4];
                ldsm4t(vb, smV + s * 16 * 272 + v_off + np * 32);
                mma16(accO[2 * np],     &pah[4 * s], vb);
                mma16(accO[2 * np + 1], &pah[4 * s], vb + 2);
            }
        }
    }

    const int bi = bh >> 4, h = bh & 15;
    const float inv0 = 1.0f / l0, inv1 = 1.0f / l1;
    const int row0 = it * 128 + r0 + lg;
    #pragma unroll
    for (int nt = 0; nt < 16; nt++) {
        const int d = 8 * nt + 2 * lp;
        *(uint32_t*)&g_attnh[((size_t)bi * T_ + row0) * C_ + h * 128 + d] =
            packh2(accO[nt][0] * inv0, accO[nt][1] * inv0);
        *(uint32_t*)&g_attnh[((size_t)bi * T_ + row0 + 8) * C_ + h * 128 + d] =
            packh2(accO[nt][2] * inv1, accO[nt][3] * inv1);
    }
}

// ---------------------------------------------------------------------------
// Launch
// ---------------------------------------------------------------------------
extern "C" void kernel_launch(void* const* d_in, const int* in_sizes, int n_in,
                              void* d_out, int out_size)
{
    const float* x = nullptr;
    const float* W_qkv = nullptr;
    const float* b_qkv = nullptr;
    const float* W_out = nullptr;
    const float* b_out = nullptr;
    int n4m_seen = 0;
    for (int i = 0; i < n_in; i++) {
        const int sz = in_sizes[i];
        if (sz == M_ * C_ && x == nullptr) x = (const float*)d_in[i];
        else if (sz == C_ * N1_) W_qkv = (const float*)d_in[i];
        else if (sz == N1_) b_qkv = (const float*)d_in[i];
        else if (sz == C_ * C_) {
            if (n4m_seen == 1) W_out = (const float*)d_in[i];
            n4m_seen++;
        }
        else if (sz == C_) b_out = (const float*)d_in[i];
    }
    float* out = (float*)d_out;

    void *xh_p, *wqkvt_p, *woutt_p, *attnh_p, *gk_p, *gv_p;
    cudaGetSymbolAddress(&xh_p, g_xh);
    cudaGetSymbolAddress(&wqkvt_p, g_wqkvt);
    cudaGetSymbolAddress(&woutt_p, g_woutt);
    cudaGetSymbolAddress(&attnh_p, g_attnh);
    cudaGetSymbolAddress(&gk_p, g_k);
    cudaGetSymbolAddress(&gv_p, g_v);

    float* kout = (out_size >= 3 * NKV) ? out + NKV : (float*)gk_p;
    float* vout = (out_size >= 3 * NKV) ? out + 2 * NKV : (float*)gv_p;

    cudaFuncSetAttribute(hgemm_kernel<0>,
                         cudaFuncAttributeMaxDynamicSharedMemorySize, GEMM_SMEM);
    cudaFuncSetAttribute(hgemm_kernel<1>,
                         cudaFuncAttributeMaxDynamicSharedMemorySize, GEMM_SMEM);
    cudaFuncSetAttribute(attn_tc_kernel,
                         cudaFuncAttributeMaxDynamicSharedMemorySize, ATTN_SMEM);

    // Fused prep: conversions/transposes + bias-init of out
    prep_kernel<<<10240, 256>>>(x, W_qkv, W_out, b_out, out);

    // qkv: N=6144 -> 48 x 32 CTAs (z=1)
    hgemm_kernel<0><<<dim3(48, 32, 1), 128, GEMM_SMEM>>>(
        (const __half*)xh_p, (const __half*)wqkvt_p, b_qkv, nullptr,
        kout, vout);
    // attention: 16 q-tiles x 32 (b,h)
    attn_tc_kernel<<<dim3(16, 32), 256, ATTN_SMEM>>>();
    // out proj: split-K=2 -> 16 x 32 x 2 CTAs, atomic partial sums
    hgemm_kernel<1><<<dim3(16, 32, 2), 128, GEMM_SMEM>>>(
        (const __half*)attnh_p, (const __half*)woutt_p, nullptr, out,
        nullptr, nullptr);
}

// round 16
// speedup vs baseline: 1.0023x; 1.0023x over previous
#include <cuda_runtime.h>
#include <cuda_fp16.h>
#include <math.h>
#include <stdint.h>

#define B_ 2
#define T_ 2048
#define C_ 2048
#define H_ 16
#define D_ 128
#define M_ (B_*T_)            /* 4096 */
#define N1_ (3*C_)            /* 6144 */
#define NKV (B_*H_*T_*D_)     /* 8388608 */

// Scratch (allocation-free)
__device__ __half g_xh[M_*C_];       // x  fp16
__device__ __half g_wqkvt[N1_*C_];   // W_qkv^T [n][k] fp16
__device__ __half g_woutt[C_*C_];    // W_out^T [n][k] fp16
__device__ __half g_qh[NKV];
__device__ __half g_kh[NKV];
__device__ __half g_vh[NKV];
__device__ float  g_k[NKV];          // fp32 k fallback
__device__ float  g_v[NKV];          // fp32 v fallback
__device__ __half g_attnh[M_*C_];    // attention out fp16
__device__ float  g_part[M_*C_];     // split-K partial (z=1)

// ---------------------------------------------------------------------------
// Helpers
// ---------------------------------------------------------------------------
__device__ __forceinline__ uint32_t smem_u32(const void* p) {
    uint32_t a;
    asm("{ .reg .u64 t; cvta.to.shared.u64 t, %1; cvt.u32.u64 %0, t; }"
        : "=r"(a) : "l"(p));
    return a;
}
__device__ __forceinline__ void cpasync16(uint32_t dst, const void* src) {
    asm volatile("cp.async.cg.shared.global [%0], [%1], 16;"
                 :: "r"(dst), "l"(src) : "memory");
}
#define CP_COMMIT() asm volatile("cp.async.commit_group;" ::: "memory")
__device__ __forceinline__ void ldsm4(uint32_t* r, uint32_t a) {
    asm volatile("ldmatrix.sync.aligned.m8n8.x4.shared.b16 {%0,%1,%2,%3}, [%4];"
                 : "=r"(r[0]), "=r"(r[1]), "=r"(r[2]), "=r"(r[3]) : "r"(a));
}
__device__ __forceinline__ void ldsm4t(uint32_t* r, uint32_t a) {
    asm volatile("ldmatrix.sync.aligned.m8n8.x4.trans.shared.b16 {%0,%1,%2,%3}, [%4];"
                 : "=r"(r[0]), "=r"(r[1]), "=r"(r[2]), "=r"(r[3]) : "r"(a));
}
__device__ __forceinline__ void mma16(float* d, const uint32_t* a,
                                      const uint32_t* b) {
    asm volatile(
        "mma.sync.aligned.m16n8k16.row.col.f32.f16.f16.f32 "
        "{%0,%1,%2,%3}, {%4,%5,%6,%7}, {%8,%9}, {%0,%1,%2,%3};"
        : "+f"(d[0]), "+f"(d[1]), "+f"(d[2]), "+f"(d[3])
        : "r"(a[0]), "r"(a[1]), "r"(a[2]), "r"(a[3]), "r"(b[0]), "r"(b[1]));
}
__device__ __forceinline__ uint32_t packh2(float lo, float hi) {
    __half2 h = __floats2half2_rn(lo, hi);
    return *(uint32_t*)&h;
}
// pack (lo,hi) fp32 -> f16x2 then 2^x on both halves (single MUFU op)
__device__ __forceinline__ uint32_t exp2_f16x2(float lo, float hi) {
    uint32_t h, r;
    asm("cvt.rn.f16x2.f32 %0, %1, %2;" : "=r"(h) : "f"(hi), "f"(lo));
    asm("ex2.approx.f16x2 %0, %1;" : "=r"(r) : "r"(h));
    return r;
}

// ---------------------------------------------------------------------------
// Fused prep (r14 layout): cvt x->f16, transpose+cvt weights.
//   [0, 6144) wqkv | [6144, 8192) wout | [8192, 9216) x cvt
// ---------------------------------------------------------------------------
__device__ __forceinline__ void transpose_body(
    const float* __restrict__ W, __half* __restrict__ Wt, int K, int N,
    int nb, int kb, float (*tile)[33])
{
    const int k0 = kb << 6, n0 = nb << 5;
    const int tx = threadIdx.x & 31, ty = threadIdx.x >> 5;
    #pragma unroll
    for (int j = 0; j < 8; j++) {
        const int kr = j * 8 + ty;
        tile[kr][tx] = __ldg(W + (size_t)(k0 + kr) * N + n0 + tx);
    }
    __syncthreads();
    #pragma unroll
    for (int j = 0; j < 4; j++) {
        const int nr = j * 8 + ty;
        const int k2 = tx * 2;
        const uint32_t p = packh2(tile[k2][nr], tile[k2 + 1][nr]);
        *(uint32_t*)&Wt[(size_t)(n0 + nr) * K + k0 + k2] = p;
    }
}

__global__ void __launch_bounds__(256) prep_kernel(
    const float* __restrict__ x,
    const float* __restrict__ Wqkv,
    const float* __restrict__ Wout)
{
    __shared__ float tile[64][33];
    const int bid = blockIdx.x;
    if (bid < 6144) {
        transpose_body(Wqkv, g_wqkvt, C_, N1_, bid % 192, bid / 192, tile);
    } else if (bid < 8192) {
        const int r = bid - 6144;
        transpose_body(Wout, g_woutt, C_, C_, r & 63, r >> 6, tile);
    } else {
        const int n4 = (M_ * C_) / 4;
        for (int i = (bid - 8192) * 256 + threadIdx.x; i < n4; i += 1024 * 256) {
            float4 v = __ldg((const float4*)x + i);
            uint2 o;
            o.x = packh2(v.x, v.y);
            o.y = packh2(v.z, v.w);
            ((uint2*)g_xh)[i] = o;
        }
    }
}

// Reduce: out = out(part0) + part1 + bias
__global__ void __launch_bounds__(256) reduce_kernel(
    float* __restrict__ out, const float* __restrict__ part,
    const float* __restrict__ bias)
{
    const int n4 = (M_ * C_) / 4;
    for (int i = blockIdx.x * 256 + threadIdx.x; i < n4;
         i += gridDim.x * 256) {
        float4 a = ((const float4*)out)[i];
        float4 b = __ldg((const float4*)part + i);
        float4 bv = *(const float4*)(bias + ((i * 4) & 2047));
        a.x += b.x + bv.x;
        a.y += b.y + bv.y;
        a.z += b.z + bv.z;
        a.w += b.w + bv.w;
        ((float4*)out)[i] = a;
    }
}

// ---------------------------------------------------------------------------
// fp16 mma.sync GEMM. CTA 128x128, BK=32, 4 warps (64x64 warp tile),
// 3-stage cp.async, 3 CTAs/SM. MODE 0: scatter qkv (z=1, bias added).
// MODE 1: split-K over gridDim.z; z=0 -> Cout, z=1 -> Kout(part buffer),
// plain stores (bias applied by reduce_kernel).
// ---------------------------------------------------------------------------
#define GSTG 20480
#define GEMM_SMEM (3 * GSTG)

template <int MODE>
__global__ void __launch_bounds__(128, 3) hgemm_kernel(
    const __half* __restrict__ Ag, const __half* __restrict__ Bt,
    const float* __restrict__ bias, float* __restrict__ Cout,
    float* __restrict__ Kout, float* __restrict__ Vout)
{
    extern __shared__ char dynsm[];
    const uint32_t smb = smem_u32(dynsm);
    const int tid  = threadIdx.x;
    const int lane = tid & 31;
    const int warp = tid >> 5;
    const int wm = warp & 1, wn = warp >> 1;
    const int bm = blockIdx.y << 7, bn = blockIdx.x << 7;
    const int lg = lane >> 2, lp = lane & 3;
    const int NIT = (2048 / 32) / gridDim.z;
    const int kb0 = blockIdx.z * NIT;

    float acc[4][8][4];
    #pragma unroll
    for (int mt = 0; mt < 4; mt++)
        #pragma unroll
        for (int nt = 0; nt < 8; nt++)
            #pragma unroll
            for (int i = 0; i < 4; i++) acc[mt][nt][i] = 0.f;

    const int l_row = tid >> 2;
    const int l_seg = tid & 3;
    auto load_tiles = [&](int it, int s) {
        const uint32_t base = smb + s * GSTG;
        #pragma unroll
        for (int j = 0; j < 4; j++) {
            const int row = l_row + 32 * j;
            cpasync16(base + row * 80 + l_seg * 16,
                      Ag + (size_t)(bm + row) * 2048 + (kb0 + it) * 32 + l_seg * 8);
            cpasync16(base + 10240 + row * 80 + l_seg * 16,
                      Bt + (size_t)(bn + row) * 2048 + (kb0 + it) * 32 + l_seg * 8);
        }
        CP_COMMIT();
    };

    const uint32_t a_off = (lane & 15) * 80 + (lane >> 4) * 16;
    const uint32_t b_off = ((lane & 7) + ((lane >> 4) & 1) * 8) * 80
                           + ((lane >> 3) & 1) * 16;

    load_tiles(0, 0);
    load_tiles(1, 1);

    #pragma unroll 1
    for (int it = 0; it < NIT; it++) {
        if (it + 2 < NIT)
            asm volatile("cp.async.wait_group 1;" ::: "memory");
        else
            asm volatile("cp.async.wait_group 0;" ::: "memory");
        __syncthreads();

        const int s = it % 3;
        const uint32_t smA = smb + s * GSTG + wm * 64 * 80 + a_off;
        const uint32_t smB = smb + s * GSTG + 10240 + wn * 64 * 80 + b_off;

        uint32_t a0[4][4], b0[4][4];
        #pragma unroll
        for (int mt = 0; mt < 4; mt++)
            ldsm4(a0[mt], smA + mt * 16 * 80);
        #pragma unroll
        for (int np = 0; np < 4; np++)
            ldsm4(b0[np], smB + np * 16 * 80);

        if (it + 2 < NIT) load_tiles(it + 2, (it + 2) % 3);

        #pragma unroll
        for (int mt = 0; mt < 4; mt++)
            #pragma unroll
            for (int np = 0; np < 4; np++) {
                mma16(acc[mt][2 * np],     a0[mt], b0[np]);
                mma16(acc[mt][2 * np + 1], a0[mt], b0[np] + 2);
            }

        uint32_t a1[4][4], b1[4][4];
        #pragma unroll
        for (int mt = 0; mt < 4; mt++)
            ldsm4(a1[mt], smA + mt * 16 * 80 + 32);
        #pragma unroll
        for (int np = 0; np < 4; np++)
            ldsm4(b1[np], smB + np * 16 * 80 + 32);
        #pragma unroll
        for (int mt = 0; mt < 4; mt++)
            #pragma unroll
            for (int np = 0; np < 4; np++) {
                mma16(acc[mt][2 * np],     a1[mt], b1[np]);
                mma16(acc[mt][2 * np + 1], a1[mt], b1[np] + 2);
            }
    }

    // Epilogue
    #pragma unroll
    for (int mt = 0; mt < 4; mt++) {
        #pragma unroll
        for (int half = 0; half < 2; half++) {
            const int m = bm + wm * 64 + mt * 16 + lg + half * 8;
            #pragma unroll
            for (int nt = 0; nt < 8; nt++) {
                const int n = bn + wn * 64 + nt * 8 + 2 * lp;
                if (MODE == 0) {
                    float2 bv = *(const float2*)(bias + n);
                    const float o0 = acc[mt][nt][half * 2 + 0] + bv.x;
                    const float o1 = acc[mt][nt][half * 2 + 1] + bv.y;
                    const int which = n >> 11;
                    const int h = (n & 2047) >> 7;
                    const int d = n & 127;
                    const int bi = m >> 11, t2 = m & 2047;
                    const size_t idx = (((size_t)bi * H_ + h) * T_ + t2) * D_ + d;
                    const uint32_t p = packh2(o0, o1);
                    if (which == 0) {
                        *(uint32_t*)&g_qh[idx] = p;
                    } else if (which == 1) {
                        *(uint32_t*)&g_kh[idx] = p;
                        *(float2*)&Kout[idx] = make_float2(o0, o1);
                    } else {
                        *(uint32_t*)&g_vh[idx] = p;
                        *(float2*)&Vout[idx] = make_float2(o0, o1);
                    }
                } else {
                    // split-K partial, plain store (no atomics, no bias)
                    float* base = (blockIdx.z == 0) ? Cout : Kout;
                    *(float2*)(base + (size_t)m * 2048 + n) =
                        make_float2(acc[mt][nt][half * 2 + 0],
                                    acc[mt][nt][half * 2 + 1]);
                }
            }
        }
    }
}

// ---------------------------------------------------------------------------
// fp16 flash attention (r14 verbatim): Br=128, Bc=32, D=128,
// Q frags ks=0..3 register-cached, exp via ex2.approx.f16x2.
// ---------------------------------------------------------------------------
#define AQ_BYTES (128 * 272)
#define AKV_BYTES (32 * 272)
#define ATTN_SMEM (AQ_BYTES + 4 * AKV_BYTES)

__global__ void __launch_bounds__(256, 2) attn_tc_kernel()
{
    extern __shared__ char dynsm[];
    const uint32_t smb = smem_u32(dynsm);
    const uint32_t smQ = smb;

    const int it  = (gridDim.x - 1) - blockIdx.x;
    const int bh  = blockIdx.y;
    const int tid = threadIdx.x;
    const int lane = tid & 31;
    const int w   = tid >> 5;
    const int lg = lane >> 2, lp = lane & 3;
    const int r0 = w * 16;

    const __half* Qg = g_qh + (size_t)bh * (T_ * D_);
    const __half* Kg = g_kh + (size_t)bh * (T_ * D_);
    const __half* Vg = g_vh + (size_t)bh * (T_ * D_);

    {
        const int row = tid >> 1;
        const int s0 = (tid & 1) * 8;
        #pragma unroll
        for (int j = 0; j < 8; j++)
            cpasync16(smQ + row * 272 + (s0 + j) * 16,
                      Qg + (size_t)(it * 128 + row) * 128 + (s0 + j) * 8);
    }
    const int kv_row = tid >> 3;
    const int kv_s0 = (tid & 7) * 2;
    auto load_kv = [&](int jt, int st) {
        const uint32_t smK = smb + AQ_BYTES + st * AKV_BYTES;
        const uint32_t smV = smb + AQ_BYTES + 2 * AKV_BYTES + st * AKV_BYTES;
        #pragma unroll
        for (int j = 0; j < 2; j++) {
            const int seg = kv_s0 + j;
            cpasync16(smK + kv_row * 272 + seg * 16,
                      Kg + (size_t)(jt * 32 + kv_row) * 128 + seg * 8);
            cpasync16(smV + kv_row * 272 + seg * 16,
                      Vg + (size_t)(jt * 32 + kv_row) * 128 + seg * 8);
        }
        CP_COMMIT();
    };
    load_kv(0, 0);

    const uint32_t q_off = (r0 + (lane & 15)) * 272 + (lane >> 4) * 16;
    const uint32_t k_off = ((lane & 7) + ((lane >> 4) & 1) * 8) * 272
                           + ((lane >> 3) & 1) * 16;
    const uint32_t v_off = ((lane & 7) + ((lane >> 3) & 1) * 8) * 272
                           + (lane >> 4) * 16;

    asm volatile("cp.async.wait_group 0;" ::: "memory");
    __syncthreads();
    load_kv(1, 1);

    uint32_t qc[4][4];
    #pragma unroll
    for (int ks = 0; ks < 4; ks++)
        ldsm4(qc[ks], smQ + q_off + ks * 32);

    float accO[16][4];
    #pragma unroll
    for (int nt = 0; nt < 16; nt++)
        #pragma unroll
        for (int i = 0; i < 4; i++) accO[nt][i] = 0.f;
    float m0 = -INFINITY, m1 = -INFINITY, l0 = 0.f, l1 = 0.f;
    const float scale = 0.08838834764831845f;
    const float L2E = 1.4426950408889634f;
    const int jmax = 4 * it + 3;
    const int rq0 = it * 128 + r0 + lg;
    const int rq1 = rq0 + 8;

    for (int jt = 0; jt <= jmax; jt++) {
        const int cur = jt & 1;
        if (jt > 0) {
            asm volatile("cp.async.wait_group 0;" ::: "memory");
            __syncthreads();
            if (jt < jmax) load_kv(jt + 1, cur ^ 1);
        }

        if (jt * 32 > it * 128 + r0 + 15) continue;

        const uint32_t smK = smb + AQ_BYTES + cur * AKV_BYTES;
        const uint32_t smV = smb + AQ_BYTES + 2 * AKV_BYTES + cur * AKV_BYTES;

        float accS[4][4];
        #pragma unroll
        for (int nt = 0; nt < 4; nt++)
            #pragma unroll
            for (int i = 0; i < 4; i++) accS[nt][i] = 0.f;
        #pragma unroll
        for (int ks = 0; ks < 8; ks++) {
            uint32_t qa[4];
            if (ks < 4) {
                qa[0] = qc[ks][0]; qa[1] = qc[ks][1];
                qa[2] = qc[ks][2]; qa[3] = qc[ks][3];
            } else {
                ldsm4(qa, smQ + q_off + ks * 32);
            }
            #pragma unroll
            for (int np = 0; np < 2; np++) {
                uint32_t kb[4];
                ldsm4(kb, smK + np * 16 * 272 + k_off + ks * 32);
                mma16(accS[2 * np],     qa, kb);
                mma16(accS[2 * np + 1], qa, kb + 2);
            }
        }

        if (jt * 32 + 31 > it * 128 + r0) {
            #pragma unroll
            for (int nt = 0; nt < 4; nt++) {
                #pragma unroll
                for (int jj = 0; jj < 2; jj++) {
                    const int ck = jt * 32 + 8 * nt + 2 * lp + jj;
                    accS[nt][jj]     = (ck > rq0) ? -INFINITY
                                                  : accS[nt][jj] * scale;
                    accS[nt][jj + 2] = (ck > rq1) ? -INFINITY
                                                  : accS[nt][jj + 2] * scale;
                }
            }
        } else {
            #pragma unroll
            for (int nt = 0; nt < 4; nt++)
                #pragma unroll
                for (int i = 0; i < 4; i++) accS[nt][i] *= scale;
        }

        float mx0 = -INFINITY, mx1 = -INFINITY;
        #pragma unroll
        for (int nt = 0; nt < 4; nt++) {
            mx0 = fmaxf(mx0, fmaxf(accS[nt][0], accS[nt][1]));
            mx1 = fmaxf(mx1, fmaxf(accS[nt][2], accS[nt][3]));
        }
        mx0 = fmaxf(mx0, __shfl_xor_sync(0xffffffffu, mx0, 1));
        mx0 = fmaxf(mx0, __shfl_xor_sync(0xffffffffu, mx0, 2));
        mx1 = fmaxf(mx1, __shfl_xor_sync(0xffffffffu, mx1, 1));
        mx1 = fmaxf(mx1, __shfl_xor_sync(0xffffffffu, mx1, 2));
        const float mn0 = fmaxf(m0, mx0), mn1 = fmaxf(m1, mx1);
        const float al0 = __expf(m0 - mn0), al1 = __expf(m1 - mn1);
        const float nb0 = -mn0 * L2E, nb1 = -mn1 * L2E;

        uint32_t pah[8];
        float s0 = 0.f, s1 = 0.f;
        #pragma unroll
        for (int nt = 0; nt < 4; nt++) {
            const float t0 = fmaf(accS[nt][0], L2E, nb0);
            const float t1 = fmaf(accS[nt][1], L2E, nb0);
            const float t2 = fmaf(accS[nt][2], L2E, nb1);
            const float t3 = fmaf(accS[nt][3], L2E, nb1);
            pah[2 * nt]     = exp2_f16x2(t0, t1);
            pah[2 * nt + 1] = exp2_f16x2(t2, t3);
            float2 f01 = __half22float2(*(__half2*)&pah[2 * nt]);
            float2 f23 = __half22float2(*(__half2*)&pah[2 * nt + 1]);
            s0 += f01.x + f01.y;
            s1 += f23.x + f23.y;
        }
        s0 += __shfl_xor_sync(0xffffffffu, s0, 1);
        s0 += __shfl_xor_sync(0xffffffffu, s0, 2);
        s1 += __shfl_xor_sync(0xffffffffu, s1, 1);
        s1 += __shfl_xor_sync(0xffffffffu, s1, 2);
        l0 = l0 * al0 + s0; m0 = mn0;
        l1 = l1 * al1 + s1; m1 = mn1;
        #pragma unroll
        for (int nt = 0; nt < 16; nt++) {
            accO[nt][0] *= al0; accO[nt][1] *= al0;
            accO[nt][2] *= al1; accO[nt][3] *= al1;
        }

        #pragma unroll
        for (int s = 0; s < 2; s++) {
            #pragma unroll
            for (int np = 0; np < 8; np++) {
                uint32_t vb[4];
                ldsm4t(vb, smV + s * 16 * 272 + v_off + np * 32);
                mma16(accO[2 * np],     &pah[4 * s], vb);
                mma16(accO[2 * np + 1], &pah[4 * s], vb + 2);
            }
        }
    }

    const int bi = bh >> 4, h = bh & 15;
    const float inv0 = 1.0f / l0, inv1 = 1.0f / l1;
    const int row0 = it * 128 + r0 + lg;
    #pragma unroll
    for (int nt = 0; nt < 16; nt++) {
        const int d = 8 * nt + 2 * lp;
        *(uint32_t*)&g_attnh[((size_t)bi * T_ + row0) * C_ + h * 128 + d] =
            packh2(accO[nt][0] * inv0, accO[nt][1] * inv0);
        *(uint32_t*)&g_attnh[((size_t)bi * T_ + row0 + 8) * C_ + h * 128 + d] =
            packh2(accO[nt][2] * inv1, accO[nt][3] * inv1);
    }
}

// ---------------------------------------------------------------------------
// Launch
// ---------------------------------------------------------------------------
extern "C" void kernel_launch(void* const* d_in, const int* in_sizes, int n_in,
                              void* d_out, int out_size)
{
    const float* x = nullptr;
    const float* W_qkv = nullptr;
    const float* b_qkv = nullptr;
    const float* W_out = nullptr;
    const float* b_out = nullptr;
    int n4m_seen = 0;
    for (int i = 0; i < n_in; i++) {
        const int sz = in_sizes[i];
        if (sz == M_ * C_ && x == nullptr) x = (const float*)d_in[i];
        else if (sz == C_ * N1_) W_qkv = (const float*)d_in[i];
        else if (sz == N1_) b_qkv = (const float*)d_in[i];
        else if (sz == C_ * C_) {
            if (n4m_seen == 1) W_out = (const float*)d_in[i];
            n4m_seen++;
        }
        else if (sz == C_) b_out = (const float*)d_in[i];
    }
    float* out = (float*)d_out;

    void *xh_p, *wqkvt_p, *woutt_p, *attnh_p, *gk_p, *gv_p, *part_p;
    cudaGetSymbolAddress(&xh_p, g_xh);
    cudaGetSymbolAddress(&wqkvt_p, g_wqkvt);
    cudaGetSymbolAddress(&woutt_p, g_woutt);
    cudaGetSymbolAddress(&attnh_p, g_attnh);
    cudaGetSymbolAddress(&gk_p, g_k);
    cudaGetSymbolAddress(&gv_p, g_v);
    cudaGetSymbolAddress(&part_p, g_part);

    float* kout = (out_size >= 3 * NKV) ? out + NKV : (float*)gk_p;
    float* vout = (out_size >= 3 * NKV) ? out + 2 * NKV : (float*)gv_p;

    cudaFuncSetAttribute(hgemm_kernel<0>,
                         cudaFuncAttributeMaxDynamicSharedMemorySize, GEMM_SMEM);
    cudaFuncSetAttribute(hgemm_kernel<1>,
                         cudaFuncAttributeMaxDynamicSharedMemorySize, GEMM_SMEM);
    cudaFuncSetAttribute(attn_tc_kernel,
                         cudaFuncAttributeMaxDynamicSharedMemorySize, ATTN_SMEM);

    prep_kernel<<<9216, 256>>>(x, W_qkv, W_out);

    // qkv: N=6144 -> 48 x 32 CTAs (z=1)
    hgemm_kernel<0><<<dim3(48, 32, 1), 128, GEMM_SMEM>>>(
        (const __half*)xh_p, (const __half*)wqkvt_p, b_qkv, nullptr,
        kout, vout);
    // attention: 16 q-tiles x 32 (b,h)
    attn_tc_kernel<<<dim3(16, 32), 256, ATTN_SMEM>>>();
    // out proj: split-K=2, z=0 -> out, z=1 -> g_part (plain stores)
    hgemm_kernel<1><<<dim3(16, 32, 2), 128, GEMM_SMEM>>>(
        (const __half*)attnh_p, (const __half*)woutt_p, nullptr, out,
        (float*)part_p, nullptr);
    // combine partials + bias
    reduce_kernel<<<1184, 256>>>(out, (const float*)part_p, b_out);
}

// round 17
// speedup vs baseline: 1.1355x; 1.1329x over previous
#include <cuda_runtime.h>
#include <cuda_fp16.h>
#include <math.h>
#include <stdint.h>

#define B_ 2
#define T_ 2048
#define C_ 2048
#define H_ 16
#define D_ 128
#define M_ (B_*T_)            /* 4096 */
#define N1_ (3*C_)            /* 6144 */
#define NKV (B_*H_*T_*D_)     /* 8388608 */

// Scratch (allocation-free)
__device__ __half g_xh[M_*C_];       // x  fp16
__device__ __half g_wqkvt[N1_*C_];   // W_qkv^T [n][k] fp16
__device__ __half g_woutt[C_*C_];    // W_out^T [n][k] fp16
__device__ __half g_qh[NKV];
__device__ __half g_kh[NKV];
__device__ __half g_vh[NKV];
__device__ float  g_k[NKV];          // fp32 k fallback
__device__ float  g_v[NKV];          // fp32 v fallback
__device__ __half g_attnh[M_*C_];    // attention out fp16

// ---------------------------------------------------------------------------
// Helpers
// ---------------------------------------------------------------------------
__device__ __forceinline__ uint32_t smem_u32(const void* p) {
    uint32_t a;
    asm("{ .reg .u64 t; cvta.to.shared.u64 t, %1; cvt.u32.u64 %0, t; }"
        : "=r"(a) : "l"(p));
    return a;
}
__device__ __forceinline__ void cpasync16(uint32_t dst, const void* src) {
    asm volatile("cp.async.cg.shared.global [%0], [%1], 16;"
                 :: "r"(dst), "l"(src) : "memory");
}
#define CP_COMMIT() asm volatile("cp.async.commit_group;" ::: "memory")
__device__ __forceinline__ void ldsm4(uint32_t* r, uint32_t a) {
    asm volatile("ldmatrix.sync.aligned.m8n8.x4.shared.b16 {%0,%1,%2,%3}, [%4];"
                 : "=r"(r[0]), "=r"(r[1]), "=r"(r[2]), "=r"(r[3]) : "r"(a));
}
__device__ __forceinline__ void ldsm4t(uint32_t* r, uint32_t a) {
    asm volatile("ldmatrix.sync.aligned.m8n8.x4.trans.shared.b16 {%0,%1,%2,%3}, [%4];"
                 : "=r"(r[0]), "=r"(r[1]), "=r"(r[2]), "=r"(r[3]) : "r"(a));
}
__device__ __forceinline__ void mma16(float* d, const uint32_t* a,
                                      const uint32_t* b) {
    asm volatile(
        "mma.sync.aligned.m16n8k16.row.col.f32.f16.f16.f32 "
        "{%0,%1,%2,%3}, {%4,%5,%6,%7}, {%8,%9}, {%0,%1,%2,%3};"
        : "+f"(d[0]), "+f"(d[1]), "+f"(d[2]), "+f"(d[3])
        : "r"(a[0]), "r"(a[1]), "r"(a[2]), "r"(a[3]), "r"(b[0]), "r"(b[1]));
}
__device__ __forceinline__ uint32_t packh2(float lo, float hi) {
    __half2 h = __floats2half2_rn(lo, hi);
    return *(uint32_t*)&h;
}
// pack (lo,hi) fp32 -> f16x2 then 2^x on both halves (single MUFU op)
__device__ __forceinline__ uint32_t exp2_f16x2(float lo, float hi) {
    uint32_t h, r;
    asm("cvt.rn.f16x2.f32 %0, %1, %2;" : "=r"(h) : "f"(hi), "f"(lo));
    asm("ex2.approx.f16x2 %0, %1;" : "=r"(r) : "r"(h));
    return r;
}

// ---------------------------------------------------------------------------
// Fused prep (r14 layout): cvt x->f16, transpose+cvt weights.
// ---------------------------------------------------------------------------
__device__ __forceinline__ void transpose_body(
    const float* __restrict__ W, __half* __restrict__ Wt, int K, int N,
    int nb, int kb, float (*tile)[33])
{
    const int k0 = kb << 6, n0 = nb << 5;
    const int tx = threadIdx.x & 31, ty = threadIdx.x >> 5;
    #pragma unroll
    for (int j = 0; j < 8; j++) {
        const int kr = j * 8 + ty;
        tile[kr][tx] = __ldg(W + (size_t)(k0 + kr) * N + n0 + tx);
    }
    __syncthreads();
    #pragma unroll
    for (int j = 0; j < 4; j++) {
        const int nr = j * 8 + ty;
        const int k2 = tx * 2;
        const uint32_t p = packh2(tile[k2][nr], tile[k2 + 1][nr]);
        *(uint32_t*)&Wt[(size_t)(n0 + nr) * K + k0 + k2] = p;
    }
}

__global__ void __launch_bounds__(256) prep_kernel(
    const float* __restrict__ x,
    const float* __restrict__ Wqkv,
    const float* __restrict__ Wout)
{
    __shared__ float tile[64][33];
    const int bid = blockIdx.x;
    if (bid < 6144) {
        transpose_body(Wqkv, g_wqkvt, C_, N1_, bid % 192, bid / 192, tile);
    } else if (bid < 8192) {
        const int r = bid - 6144;
        transpose_body(Wout, g_woutt, C_, C_, r & 63, r >> 6, tile);
    } else {
        const int n4 = (M_ * C_) / 4;
        for (int i = (bid - 8192) * 256 + threadIdx.x; i < n4; i += 1024 * 256) {
            float4 v = __ldg((const float4*)x + i);
            uint2 o;
            o.x = packh2(v.x, v.y);
            o.y = packh2(v.z, v.w);
            ((uint2*)g_xh)[i] = o;
        }
    }
}

// ---------------------------------------------------------------------------
// fp16 mma.sync GEMM (r14 verbatim): CTA 128x128, BK=32, 4 warps, 3-stage.
// MODE 0: scatter qkv + fp32 k/v; MODE 1: plain store with bias.
// ---------------------------------------------------------------------------
#define GSTG 20480
#define GEMM_SMEM (3 * GSTG)

template <int MODE>
__global__ void __launch_bounds__(128, 3) hgemm_kernel(
    const __half* __restrict__ Ag, const __half* __restrict__ Bt,
    const float* __restrict__ bias, float* __restrict__ Cout,
    float* __restrict__ Kout, float* __restrict__ Vout)
{
    extern __shared__ char dynsm[];
    const uint32_t smb = smem_u32(dynsm);
    const int tid  = threadIdx.x;
    const int lane = tid & 31;
    const int warp = tid >> 5;
    const int wm = warp & 1, wn = warp >> 1;
    const int bm = blockIdx.y << 7, bn = blockIdx.x << 7;
    const int lg = lane >> 2, lp = lane & 3;

    float acc[4][8][4];
    #pragma unroll
    for (int mt = 0; mt < 4; mt++)
        #pragma unroll
        for (int nt = 0; nt < 8; nt++)
            #pragma unroll
            for (int i = 0; i < 4; i++) acc[mt][nt][i] = 0.f;

    const int l_row = tid >> 2;
    const int l_seg = tid & 3;
    auto load_tiles = [&](int it, int s) {
        const uint32_t base = smb + s * GSTG;
        #pragma unroll
        for (int j = 0; j < 4; j++) {
            const int row = l_row + 32 * j;
            cpasync16(base + row * 80 + l_seg * 16,
                      Ag + (size_t)(bm + row) * 2048 + it * 32 + l_seg * 8);
            cpasync16(base + 10240 + row * 80 + l_seg * 16,
                      Bt + (size_t)(bn + row) * 2048 + it * 32 + l_seg * 8);
        }
        CP_COMMIT();
    };

    const uint32_t a_off = (lane & 15) * 80 + (lane >> 4) * 16;
    const uint32_t b_off = ((lane & 7) + ((lane >> 4) & 1) * 8) * 80
                           + ((lane >> 3) & 1) * 16;

    const int NIT = 2048 / 32;  // 64
    load_tiles(0, 0);
    load_tiles(1, 1);

    #pragma unroll 1
    for (int it = 0; it < NIT; it++) {
        if (it + 2 < NIT)
            asm volatile("cp.async.wait_group 1;" ::: "memory");
        else
            asm volatile("cp.async.wait_group 0;" ::: "memory");
        __syncthreads();

        const int s = it % 3;
        const uint32_t smA = smb + s * GSTG + wm * 64 * 80 + a_off;
        const uint32_t smB = smb + s * GSTG + 10240 + wn * 64 * 80 + b_off;

        uint32_t a0[4][4], b0[4][4];
        #pragma unroll
        for (int mt = 0; mt < 4; mt++)
            ldsm4(a0[mt], smA + mt * 16 * 80);
        #pragma unroll
        for (int np = 0; np < 4; np++)
            ldsm4(b0[np], smB + np * 16 * 80);

        if (it + 2 < NIT) load_tiles(it + 2, (it + 2) % 3);

        #pragma unroll
        for (int mt = 0; mt < 4; mt++)
            #pragma unroll
            for (int np = 0; np < 4; np++) {
                mma16(acc[mt][2 * np],     a0[mt], b0[np]);
                mma16(acc[mt][2 * np + 1], a0[mt], b0[np] + 2);
            }

        uint32_t a1[4][4], b1[4][4];
        #pragma unroll
        for (int mt = 0; mt < 4; mt++)
            ldsm4(a1[mt], smA + mt * 16 * 80 + 32);
        #pragma unroll
        for (int np = 0; np < 4; np++)
            ldsm4(b1[np], smB + np * 16 * 80 + 32);
        #pragma unroll
        for (int mt = 0; mt < 4; mt++)
            #pragma unroll
            for (int np = 0; np < 4; np++) {
                mma16(acc[mt][2 * np],     a1[mt], b1[np]);
                mma16(acc[mt][2 * np + 1], a1[mt], b1[np] + 2);
            }
    }

    // Epilogue
    #pragma unroll
    for (int mt = 0; mt < 4; mt++) {
        #pragma unroll
        for (int half = 0; half < 2; half++) {
            const int m = bm + wm * 64 + mt * 16 + lg + half * 8;
            #pragma unroll
            for (int nt = 0; nt < 8; nt++) {
                const int n = bn + wn * 64 + nt * 8 + 2 * lp;
                float2 bv = *(const float2*)(bias + n);
                const float o0 = acc[mt][nt][half * 2 + 0] + bv.x;
                const float o1 = acc[mt][nt][half * 2 + 1] + bv.y;
                if (MODE == 0) {
                    const int which = n >> 11;
                    const int h = (n & 2047) >> 7;
                    const int d = n & 127;
                    const int bi = m >> 11, t2 = m & 2047;
                    const size_t idx = (((size_t)bi * H_ + h) * T_ + t2) * D_ + d;
                    const uint32_t p = packh2(o0, o1);
                    if (which == 0) {
                        *(uint32_t*)&g_qh[idx] = p;
                    } else if (which == 1) {
                        *(uint32_t*)&g_kh[idx] = p;
                        *(float2*)&Kout[idx] = make_float2(o0, o1);
                    } else {
                        *(uint32_t*)&g_vh[idx] = p;
                        *(float2*)&Vout[idx] = make_float2(o0, o1);
                    }
                } else {
                    *(float2*)(Cout + (size_t)m * 2048 + n) = make_float2(o0, o1);
                }
            }
        }
    }
}

// ---------------------------------------------------------------------------
// fp16 flash attention, causal. Br=128, Bc=32, D=128. 4-stage KV pipeline,
// TWO key-tiles per barrier (halves __syncthreads count vs r14).
// Q frags ks=0..3 register-cached; exp via ex2.approx.f16x2.
// ---------------------------------------------------------------------------
#define AQ_BYTES (128 * 272)
#define AKV_BYTES (32 * 272)
#define ATTN_SMEM (AQ_BYTES + 8 * AKV_BYTES)   /* 34816 + 69632 = 104448 */

__global__ void __launch_bounds__(256, 2) attn_tc_kernel()
{
    extern __shared__ char dynsm[];
    const uint32_t smb = smem_u32(dynsm);
    const uint32_t smQ = smb;

    const int it  = (gridDim.x - 1) - blockIdx.x;
    const int bh  = blockIdx.y;
    const int tid = threadIdx.x;
    const int lane = tid & 31;
    const int w   = tid >> 5;
    const int lg = lane >> 2, lp = lane & 3;
    const int r0 = w * 16;

    const __half* Qg = g_qh + (size_t)bh * (T_ * D_);
    const __half* Kg = g_kh + (size_t)bh * (T_ * D_);
    const __half* Vg = g_vh + (size_t)bh * (T_ * D_);

    // Q tile (bundled into KV0's commit group)
    {
        const int row = tid >> 1;
        const int s0 = (tid & 1) * 8;
        #pragma unroll
        for (int j = 0; j < 8; j++)
            cpasync16(smQ + row * 272 + (s0 + j) * 16,
                      Qg + (size_t)(it * 128 + row) * 128 + (s0 + j) * 8);
    }
    const int kv_row = tid >> 3;
    const int kv_s0 = (tid & 7) * 2;
    // 4 stages: K at AQ + st*AKV, V at AQ + 4*AKV + st*AKV
    auto load_kv = [&](int jt) {
        const int st = jt & 3;
        const uint32_t smK = smb + AQ_BYTES + st * AKV_BYTES;
        const uint32_t smV = smb + AQ_BYTES + 4 * AKV_BYTES + st * AKV_BYTES;
        #pragma unroll
        for (int j = 0; j < 2; j++) {
            const int seg = kv_s0 + j;
            cpasync16(smK + kv_row * 272 + seg * 16,
                      Kg + (size_t)(jt * 32 + kv_row) * 128 + seg * 8);
            cpasync16(smV + kv_row * 272 + seg * 16,
                      Vg + (size_t)(jt * 32 + kv_row) * 128 + seg * 8);
        }
        CP_COMMIT();
    };
    load_kv(0);      // group: Q + KV0
    load_kv(1);

    const uint32_t q_off = (r0 + (lane & 15)) * 272 + (lane >> 4) * 16;
    const uint32_t k_off = ((lane & 7) + ((lane >> 4) & 1) * 8) * 272
                           + ((lane >> 3) & 1) * 16;
    const uint32_t v_off = ((lane & 7) + ((lane >> 3) & 1) * 8) * 272
                           + (lane >> 4) * 16;

    asm volatile("cp.async.wait_group 0;" ::: "memory");
    __syncthreads();

    uint32_t qc[4][4];
    #pragma unroll
    for (int ks = 0; ks < 4; ks++)
        ldsm4(qc[ks], smQ + q_off + ks * 32);

    float accO[16][4];
    #pragma unroll
    for (int nt = 0; nt < 16; nt++)
        #pragma unroll
        for (int i = 0; i < 4; i++) accO[nt][i] = 0.f;
    float m0 = -INFINITY, m1 = -INFINITY, l0 = 0.f, l1 = 0.f;
    const float scale = 0.08838834764831845f;
    const float L2E = 1.4426950408889634f;
    const int jmax = 4 * it + 3;                // odd -> even pair count
    const int rq0 = it * 128 + r0 + lg;
    const int rq1 = rq0 + 8;

    // one key-tile compute (stage jt&3)
    auto compute_tile = [&](int jt) {
        if (jt * 32 > it * 128 + r0 + 15) return;   // warp-level causal skip
        const int st = jt & 3;
        const uint32_t smK = smb + AQ_BYTES + st * AKV_BYTES;
        const uint32_t smV = smb + AQ_BYTES + 4 * AKV_BYTES + st * AKV_BYTES;

        float accS[4][4];
        #pragma unroll
        for (int nt = 0; nt < 4; nt++)
            #pragma unroll
            for (int i = 0; i < 4; i++) accS[nt][i] = 0.f;
        #pragma unroll
        for (int ks = 0; ks < 8; ks++) {
            uint32_t qa[4];
            if (ks < 4) {
                qa[0] = qc[ks][0]; qa[1] = qc[ks][1];
                qa[2] = qc[ks][2]; qa[3] = qc[ks][3];
            } else {
                ldsm4(qa, smQ + q_off + ks * 32);
            }
            #pragma unroll
            for (int np = 0; np < 2; np++) {
                uint32_t kb[4];
                ldsm4(kb, smK + np * 16 * 272 + k_off + ks * 32);
                mma16(accS[2 * np],     qa, kb);
                mma16(accS[2 * np + 1], qa, kb + 2);
            }
        }

        if (jt * 32 + 31 > it * 128 + r0) {
            #pragma unroll
            for (int nt = 0; nt < 4; nt++) {
                #pragma unroll
                for (int jj = 0; jj < 2; jj++) {
                    const int ck = jt * 32 + 8 * nt + 2 * lp + jj;
                    accS[nt][jj]     = (ck > rq0) ? -INFINITY
                                                  : accS[nt][jj] * scale;
                    accS[nt][jj + 2] = (ck > rq1) ? -INFINITY
                                                  : accS[nt][jj + 2] * scale;
                }
            }
        } else {
            #pragma unroll
            for (int nt = 0; nt < 4; nt++)
                #pragma unroll
                for (int i = 0; i < 4; i++) accS[nt][i] *= scale;
        }

        float mx0 = -INFINITY, mx1 = -INFINITY;
        #pragma unroll
        for (int nt = 0; nt < 4; nt++) {
            mx0 = fmaxf(mx0, fmaxf(accS[nt][0], accS[nt][1]));
            mx1 = fmaxf(mx1, fmaxf(accS[nt][2], accS[nt][3]));
        }
        mx0 = fmaxf(mx0, __shfl_xor_sync(0xffffffffu, mx0, 1));
        mx0 = fmaxf(mx0, __shfl_xor_sync(0xffffffffu, mx0, 2));
        mx1 = fmaxf(mx1, __shfl_xor_sync(0xffffffffu, mx1, 1));
        mx1 = fmaxf(mx1, __shfl_xor_sync(0xffffffffu, mx1, 2));
        const float mn0 = fmaxf(m0, mx0), mn1 = fmaxf(m1, mx1);
        const float al0 = __expf(m0 - mn0), al1 = __expf(m1 - mn1);
        const float nb0 = -mn0 * L2E, nb1 = -mn1 * L2E;

        uint32_t pah[8];
        float s0 = 0.f, s1 = 0.f;
        #pragma unroll
        for (int nt = 0; nt < 4; nt++) {
            const float t0 = fmaf(accS[nt][0], L2E, nb0);
            const float t1 = fmaf(accS[nt][1], L2E, nb0);
            const float t2 = fmaf(accS[nt][2], L2E, nb1);
            const float t3 = fmaf(accS[nt][3], L2E, nb1);
            pah[2 * nt]     = exp2_f16x2(t0, t1);
            pah[2 * nt + 1] = exp2_f16x2(t2, t3);
            float2 f01 = __half22float2(*(__half2*)&pah[2 * nt]);
            float2 f23 = __half22float2(*(__half2*)&pah[2 * nt + 1]);
            s0 += f01.x + f01.y;
            s1 += f23.x + f23.y;
        }
        s0 += __shfl_xor_sync(0xffffffffu, s0, 1);
        s0 += __shfl_xor_sync(0xffffffffu, s0, 2);
        s1 += __shfl_xor_sync(0xffffffffu, s1, 1);
        s1 += __shfl_xor_sync(0xffffffffu, s1, 2);
        l0 = l0 * al0 + s0; m0 = mn0;
        l1 = l1 * al1 + s1; m1 = mn1;
        #pragma unroll
        for (int nt = 0; nt < 16; nt++) {
            accO[nt][0] *= al0; accO[nt][1] *= al0;
            accO[nt][2] *= al1; accO[nt][3] *= al1;
        }

        #pragma unroll
        for (int s = 0; s < 2; s++) {
            #pragma unroll
            for (int np = 0; np < 8; np++) {
                uint32_t vb[4];
                ldsm4t(vb, smV + s * 16 * 272 + v_off + np * 32);
                mma16(accO[2 * np],     &pah[4 * s], vb);
                mma16(accO[2 * np + 1], &pah[4 * s], vb + 2);
            }
        }
    };

    #pragma unroll 1
    for (int jt2 = 0; jt2 <= jmax; jt2 += 2) {
        if (jt2 > 0) {
            asm volatile("cp.async.wait_group 0;" ::: "memory");
            __syncthreads();
        }
        if (jt2 + 2 <= jmax) load_kv(jt2 + 2);
        if (jt2 + 3 <= jmax) load_kv(jt2 + 3);
        compute_tile(jt2);
        compute_tile(jt2 + 1);
    }

    const int bi = bh >> 4, h = bh & 15;
    const float inv0 = 1.0f / l0, inv1 = 1.0f / l1;
    const int row0 = it * 128 + r0 + lg;
    #pragma unroll
    for (int nt = 0; nt < 16; nt++) {
        const int d = 8 * nt + 2 * lp;
        *(uint32_t*)&g_attnh[((size_t)bi * T_ + row0) * C_ + h * 128 + d] =
            packh2(accO[nt][0] * inv0, accO[nt][1] * inv0);
        *(uint32_t*)&g_attnh[((size_t)bi * T_ + row0 + 8) * C_ + h * 128 + d] =
            packh2(accO[nt][2] * inv1, accO[nt][3] * inv1);
    }
}

// ---------------------------------------------------------------------------
// Launch
// ---------------------------------------------------------------------------
extern "C" void kernel_launch(void* const* d_in, const int* in_sizes, int n_in,
                              void* d_out, int out_size)
{
    const float* x = nullptr;
    const float* W_qkv = nullptr;
    const float* b_qkv = nullptr;
    const float* W_out = nullptr;
    const float* b_out = nullptr;
    int n4m_seen = 0;
    for (int i = 0; i < n_in; i++) {
        const int sz = in_sizes[i];
        if (sz == M_ * C_ && x == nullptr) x = (const float*)d_in[i];
        else if (sz == C_ * N1_) W_qkv = (const float*)d_in[i];
        else if (sz == N1_) b_qkv = (const float*)d_in[i];
        else if (sz == C_ * C_) {
            if (n4m_seen == 1) W_out = (const float*)d_in[i];
            n4m_seen++;
        }
        else if (sz == C_) b_out = (const float*)d_in[i];
    }
    float* out = (float*)d_out;

    void *xh_p, *wqkvt_p, *woutt_p, *attnh_p, *gk_p, *gv_p;
    cudaGetSymbolAddress(&xh_p, g_xh);
    cudaGetSymbolAddress(&wqkvt_p, g_wqkvt);
    cudaGetSymbolAddress(&woutt_p, g_woutt);
    cudaGetSymbolAddress(&attnh_p, g_attnh);
    cudaGetSymbolAddress(&gk_p, g_k);
    cudaGetSymbolAddress(&gv_p, g_v);

    float* kout = (out_size >= 3 * NKV) ? out + NKV : (float*)gk_p;
    float* vout = (out_size >= 3 * NKV) ? out + 2 * NKV : (float*)gv_p;

    cudaFuncSetAttribute(hgemm_kernel<0>,
                         cudaFuncAttributeMaxDynamicSharedMemorySize, GEMM_SMEM);
    cudaFuncSetAttribute(hgemm_kernel<1>,
                         cudaFuncAttributeMaxDynamicSharedMemorySize, GEMM_SMEM);
    cudaFuncSetAttribute(attn_tc_kernel,
                         cudaFuncAttributeMaxDynamicSharedMemorySize, ATTN_SMEM);

    prep_kernel<<<9216, 256>>>(x, W_qkv, W_out);

    // qkv: N=6144 -> 48 x 32 CTAs
    hgemm_kernel<0><<<dim3(48, 32), 128, GEMM_SMEM>>>(
        (const __half*)xh_p, (const __half*)wqkvt_p, b_qkv, nullptr,
        kout, vout);
    // attention: 16 q-tiles x 32 (b,h)
    attn_tc_kernel<<<dim3(16, 32), 256, ATTN_SMEM>>>();
    // out proj: N=2048 -> 16 x 32 CTAs (r14 config, z=1, bias in epilogue)
    hgemm_kernel<1><<<dim3(16, 32), 128, GEMM_SMEM>>>(
        (const __half*)attnh_p, (const __half*)woutt_p, b_out, out,
        nullptr, nullptr);
}